// round 16
// baseline (speedup 1.0000x reference)
#include <cuda_runtime.h>
#include <math.h>
#include <stdint.h>

// ---------------- problem constants ----------------
#define IMG      1024
#define FEAT     256          // backbone output spatial
#define CB       128          // backbone channels
#define FM       254          // head conv output spatial
#define NHEAD    48           // 45 head outputs (9 cls + 36 reg), padded to 48
#define NPOS     (FM*FM)      // 64516 positions
#define N_ANCH   (NPOS*9)     // 580644 anchors
#define K_GT     16
#define NB_FOLD  288
#define NB_BACK  512
#define NB_PREP  (NB_BACK + NB_FOLD + 1)   // 801

// head kernel smem geometry (dy-outer: 24 phases, 3 dx taps per phase)
#define BSTR 20               // Bs row stride (words)
#define AKS  56               // As k-row stride (words)
#define AS_TAP   (16*AKS)     // 896 words per dx tap
#define AS_WORDS (3*AS_TAP)   // 2688 per buffer (3 dx taps)
#define BS_WORDS (260*BSTR)   // 5200 per buffer
#define HDSMEM  ((2*AS_WORDS + 2*BS_WORDS) * 4)   // 63104 B
#define OSTR 49               // output staging stride (conflict-free)

// ---------------- scratch (static device memory; no allocation) ----------------
__device__ float d_feats[FEAT*FEAT*CB];        // 32 MB (tf32-rounded values)
__device__ float d_wf   [9*CB*NHEAD];          // folded head weights (tf32)
__device__ float d_bfold[NHEAD];
__device__ float d_maxiou[N_ANCH];             // per-anchor max IoU (pass1)
__device__ unsigned int d_gtpart[NB_FOLD*K_GT];// per-fold-block per-gt max keys (overwritten each launch)
__device__ double d_acc[4];                    // cls_sum, sel_cnt, box_sum, pos_cnt (self-resetting)
__device__ unsigned int d_cnt;                 // ticket (self-resetting)

// ---------------- helpers ----------------
__device__ __forceinline__ unsigned int fkey(float f) {
    unsigned int u = __float_as_uint(f);
    return (u & 0x80000000u) ? ~u : (u | 0x80000000u);
}
__device__ __forceinline__ float fdecode(unsigned int k) {
    return (k & 0x80000000u) ? __uint_as_float(k & 0x7fffffffu) : __uint_as_float(~k);
}
__device__ __forceinline__ float to_tf32(float x) {
    uint32_t r;
    asm("cvt.rna.tf32.f32 %0, %1;" : "=r"(r) : "f"(x));
    return __uint_as_float(r);
}
__device__ __forceinline__ void cp16(uint32_t dst_s, const void* src) {
    asm volatile("cp.async.ca.shared.global [%0], [%1], 16;" :: "r"(dst_s), "l"(src));
}

// IoU with exact, non-contracted fp32 op order (matches the reference formula).
__device__ __forceinline__ float iou_exact(float ax1, float ay1, float ax2, float ay2,
                                           float gx1, float gy1, float gx2, float gy2) {
    const float g = 1.0f / 1024.0f;   // exact in fp32
    float s1 = __fmul_rn(__fadd_rn(__fadd_rn(ax2, -ax1), g),
                         __fadd_rn(__fadd_rn(ay2, -ay1), g));
    float s2 = __fmul_rn(__fadd_rn(__fadd_rn(gx2, -gx1), g),
                         __fadd_rn(__fadd_rn(gy2, -gy1), g));
    float xa = fmaxf(ax1, gx1), ya = fmaxf(ay1, gy1);
    float xb = fminf(ax2, gx2), yb = fminf(ay2, gy2);
    float iw = fmaxf(__fadd_rn(__fadd_rn(xb, -xa), g), 0.0f);
    float ih = fmaxf(__fadd_rn(__fadd_rn(yb, -ya), g), 0.0f);
    float inter = __fmul_rn(iw, ih);
    return __fdiv_rn(inter, __fadd_rn(__fadd_rn(s1, s2), -inter));
}

// anchor box (u -> x grid, v -> y grid, a -> ratio/scale)
__device__ __forceinline__ void anchor_box(int u, int v, int a,
                                           float& x1, float& y1, float& x2, float& y2,
                                           bool& inside) {
    const double STEP = 1.0 / 254.0;
    float cx = (float)((double)u * STEP);
    float cy = (float)((double)v * STEP);
    const float RAT[3] = {0.5f, 1.0f, 2.0f};
    const float SCL[3] = {0.2f, 0.4f, 0.7f};
    int ri = a / 3;
    int si = a - ri * 3;
    float r = sqrtf(RAT[ri]);
    float s = SCL[si];
    float w = __fmul_rn(s, r);
    float h = __fdiv_rn(s, r);
    float hwp = __fmul_rn(w, 0.5f);
    float hhp = __fmul_rn(h, 0.5f);
    float hwn = __fmul_rn(hwp, -1.0f);
    float hhn = __fmul_rn(hhp, -1.0f);
    x1 = __fadd_rn(cx, hwn);
    y1 = __fadd_rn(cy, hhn);
    x2 = __fadd_rn(cx, hwp);
    y2 = __fadd_rn(cy, hhp);
    inside = (x1 >= 0.0f) && (y1 >= 0.0f) && (x2 < 1.0f) && (y2 < 1.0f);
}

__device__ __forceinline__ float softplus_f(float x) {
    return fmaxf(x, 0.0f) + log1pf(expf(-fabsf(x)));
}

__device__ __forceinline__ void mma_tf32(float* acc,
                                         uint32_t a0, uint32_t a1, uint32_t a2, uint32_t a3,
                                         uint32_t b0, uint32_t b1) {
    asm volatile("mma.sync.aligned.m16n8k8.row.col.f32.tf32.tf32.f32 "
                 "{%0,%1,%2,%3}, {%4,%5,%6,%7}, {%8,%9}, {%0,%1,%2,%3};"
                 : "+f"(acc[0]), "+f"(acc[1]), "+f"(acc[2]), "+f"(acc[3])
                 : "r"(a0), "r"(a1), "r"(a2), "r"(a3), "r"(b0), "r"(b1));
}

// ================= kernel 1: mega_prep =================
// blocks [0,512): backbone conv (tf32 MMA GEMM)
// blocks [512,800): fold_w + pass1 slice
// block  800: fold_b
#define BKS 52
extern __shared__ float msm[];
__global__ __launch_bounds__(256) void mega_prep_kernel(
        const float* __restrict__ img, const float* __restrict__ Wb,
        const float* __restrict__ bb,  const float* __restrict__ Wi,
        const float* __restrict__ bi,  const float* __restrict__ Wc,
        const float* __restrict__ bc,  const float* __restrict__ Wr,
        const float* __restrict__ br,  const float* __restrict__ gt) {
    int b = blockIdx.x;
    int tid = threadIdx.x;

    if (b < NB_BACK) {
        // ---------- backbone ----------
        float* Wh = msm;                   // [128][BKS]
        float* Bs = msm + CB * BKS;        // [128][BKS]
        float* sb = msm + 2 * CB * BKS;    // [128]
        int oy  = b >> 1;
        int ox0 = (b & 1) * 128;

        #pragma unroll
        for (int i = tid; i < 6144; i += 256) {
            int o = i / 48, k = i - (i / 48) * 48;
            Wh[o * BKS + k] = to_tf32(Wb[k * CB + o]);
        }
        if (tid < 128) sb[tid] = bb[tid];

        int oy4 = oy * 4;
        #pragma unroll
        for (int i = tid; i < 1536; i += 256) {
            int p = i / 12, j = i - (i / 12) * 12;
            const float* src = img + (oy4 + j / 3) * 3072 + (ox0 + p) * 12 + (j % 3) * 4;
            float4 v = *(const float4*)src;
            float* dst = &Bs[p * BKS + j * 4];
            dst[0] = to_tf32(v.x); dst[1] = to_tf32(v.y);
            dst[2] = to_tf32(v.z); dst[3] = to_tf32(v.w);
        }
        __syncthreads();

        int warp = tid >> 5, lane = tid & 31;
        int g = lane >> 2, q = lane & 3;

        float acc[8][2][4];
        #pragma unroll
        for (int mt = 0; mt < 8; mt++)
            #pragma unroll
            for (int nt = 0; nt < 2; nt++)
                #pragma unroll
                for (int i = 0; i < 4; i++) acc[mt][nt][i] = 0.0f;

        #pragma unroll
        for (int ks = 0; ks < 6; ks++) {
            uint32_t bf[2][2];
            #pragma unroll
            for (int nt = 0; nt < 2; nt++) {
                int m = warp * 16 + nt * 8 + g;
                bf[nt][0] = __float_as_uint(Bs[m * BKS + ks * 8 + q]);
                bf[nt][1] = __float_as_uint(Bs[m * BKS + ks * 8 + q + 4]);
            }
            #pragma unroll
            for (int mt = 0; mt < 8; mt++) {
                uint32_t a0 = __float_as_uint(Wh[(mt * 16 + g    ) * BKS + ks * 8 + q    ]);
                uint32_t a1 = __float_as_uint(Wh[(mt * 16 + g + 8) * BKS + ks * 8 + q    ]);
                uint32_t a2 = __float_as_uint(Wh[(mt * 16 + g    ) * BKS + ks * 8 + q + 4]);
                uint32_t a3 = __float_as_uint(Wh[(mt * 16 + g + 8) * BKS + ks * 8 + q + 4]);
                #pragma unroll
                for (int nt = 0; nt < 2; nt++)
                    mma_tf32(acc[mt][nt], a0, a1, a2, a3, bf[nt][0], bf[nt][1]);
            }
        }

        #pragma unroll
        for (int mt = 0; mt < 8; mt++) {
            float b0 = sb[mt * 16 + g];
            float b1 = sb[mt * 16 + g + 8];
            #pragma unroll
            for (int nt = 0; nt < 2; nt++) {
                int p0 = warp * 16 + nt * 8 + 2 * q;
                #pragma unroll
                for (int c = 0; c < 2; c++) {
                    int p = p0 + c;
                    float* o = &d_feats[(oy * FEAT + ox0 + p) * CB + mt * 16 + g];
                    o[0] = to_tf32(acc[mt][nt][0 + c] + b0);
                    o[8] = to_tf32(acc[mt][nt][2 + c] + b1);
                }
            }
        }
    } else if (b < NB_BACK + NB_FOLD) {
        // ---------- fold_w + pass1 slice ----------
        __shared__ float wrow[4][256];
        __shared__ float sgt[K_GT * 4];
        __shared__ unsigned int skey[K_GT];
        int fb = b - NB_BACK;
        if (tid < K_GT * 4) sgt[tid] = gt[tid];
        if (tid < K_GT)     skey[tid] = 0u;

        int sb4 = tid >> 6;               // sub-block 0..3
        int t2  = tid & 63;
        int r   = fb * 4 + sb4;           // 1152 rows total
        #pragma unroll
        for (int i = 0; i < 4; i++)
            wrow[sb4][t2 + 64 * i] = Wi[r * 256 + t2 + 64 * i];
        __syncthreads();
        if (t2 < NHEAD) {
            const float* w = wrow[sb4];
            float acc = 0.0f;
            if (t2 < 45) {
                float p0 = 0.f, p1 = 0.f, p2 = 0.f, p3 = 0.f;
                if (t2 < 9) {
                    #pragma unroll 4
                    for (int m = 0; m < 256; m += 4) {
                        p0 += wrow[sb4][m + 0] * Wc[(m + 0) * 9 + t2];
                        p1 += wrow[sb4][m + 1] * Wc[(m + 1) * 9 + t2];
                        p2 += wrow[sb4][m + 2] * Wc[(m + 2) * 9 + t2];
                        p3 += wrow[sb4][m + 3] * Wc[(m + 3) * 9 + t2];
                    }
                } else {
                    int o = t2 - 9;
                    #pragma unroll 4
                    for (int m = 0; m < 256; m += 4) {
                        p0 += wrow[sb4][m + 0] * Wr[(m + 0) * 36 + o];
                        p1 += wrow[sb4][m + 1] * Wr[(m + 1) * 36 + o];
                        p2 += wrow[sb4][m + 2] * Wr[(m + 2) * 36 + o];
                        p3 += wrow[sb4][m + 3] * Wr[(m + 3) * 36 + o];
                    }
                }
                acc = (p0 + p1) + (p2 + p3);
            }
            (void)w;
            d_wf[r * NHEAD + t2] = to_tf32(acc);
        }

        // pass1 slice: per-gt max IoU + per-anchor maxiou store
        float mg[K_GT];
        #pragma unroll
        for (int g2 = 0; g2 < K_GT; g2++) mg[g2] = -1.0f;
        for (int n = fb * 256 + tid; n < N_ANCH; n += NB_FOLD * 256) {
            int u = n / (FM * 9);
            int rem = n - u * (FM * 9);
            int v = rem / 9;
            int a = rem - v * 9;
            float x1, y1, x2, y2; bool inside;
            anchor_box(u, v, a, x1, y1, x2, y2, inside);
            float mi = -1.0f;
            if (inside) {
                #pragma unroll
                for (int g2 = 0; g2 < K_GT; g2++) {
                    float io = iou_exact(x1, y1, x2, y2,
                                         sgt[g2 * 4 + 0], sgt[g2 * 4 + 1],
                                         sgt[g2 * 4 + 2], sgt[g2 * 4 + 3]);
                    mi = fmaxf(mi, io);
                    mg[g2] = fmaxf(mg[g2], io);
                }
            }
            d_maxiou[n] = mi;
        }
        int lane = tid & 31;
        #pragma unroll
        for (int g2 = 0; g2 < K_GT; g2++) {
            float m = mg[g2];
            #pragma unroll
            for (int off = 16; off > 0; off >>= 1)
                m = fmaxf(m, __shfl_xor_sync(0xffffffffu, m, off));
            if (lane == 0) atomicMax(&skey[g2], fkey(m));
        }
        __syncthreads();
        if (tid < K_GT) d_gtpart[fb * K_GT + tid] = skey[tid];   // plain store, no init needed
    } else {
        // ---------- fold_b (8 warps, split-K) ----------
        int w = tid >> 5, lane = tid & 31;
        #pragma unroll
        for (int r = 0; r < 6; r++) {
            int o = w + 8 * r;            // 0..47
            float part = 0.0f;
            if (o < 45) {
                #pragma unroll
                for (int i = 0; i < 8; i++) {
                    int m = lane + 32 * i;
                    float bim = bi[m];
                    part += (o < 9) ? bim * Wc[m * 9 + o] : bim * Wr[m * 36 + (o - 9)];
                }
            }
            #pragma unroll
            for (int off = 16; off > 0; off >>= 1)
                part += __shfl_xor_sync(0xffffffffu, part, off);
            if (lane == 0) {
                float bias = (o < 9) ? bc[o] : (o < 45 ? br[o - 9] : 0.0f);
                d_bfold[o] = (o < 45) ? part + bias : 0.0f;
            }
        }
    }
}

// ---------------- kernel 2: head conv (1-sync pipeline) + pruned fused loss ----------------
extern __shared__ float hsm[];
__global__ __launch_bounds__(256, 2) void head_mma_kernel(const float* __restrict__ gt,
                                                          float* __restrict__ out) {
    float* Asb[2] = { hsm,              hsm + AS_WORDS };
    float* Bsb[2] = { hsm + 2*AS_WORDS, hsm + 2*AS_WORDS + BS_WORDS };
    __shared__ float sgt[K_GT * 4];
    __shared__ float sgm[K_GT];
    __shared__ unsigned int skeyh[K_GT];
    __shared__ double sacc[4];
    __shared__ bool slast;
    int tid  = threadIdx.x;
    int u    = blockIdx.x;
    int warp = tid >> 5, lane = tid & 31;
    int g = lane >> 2, q = lane & 3;

    if (tid < K_GT * 4) sgt[tid] = gt[tid];
    if (tid < K_GT)     skeyh[tid] = 0u;
    if (tid < 4)        sacc[tid] = 0.0;

    auto issue_fill = [&](int p, int buf) {
        int dy = p >> 3;
        int c0 = (p & 7) << 4;
        #pragma unroll
        for (int j = 0; j < 3; j++) {
            int idx = tid + 256 * j;
            if (idx < 576) {
                int dx = idx / 192, rem = idx - dx * 192;
                int k = rem / 12, o4 = (rem - (rem / 12) * 12) * 4;
                uint32_t d = (uint32_t)__cvta_generic_to_shared(
                    &Asb[buf][dx * AS_TAP + k * AKS + o4]);
                cp16(d, d_wf + ((dy * 3 + dx) * CB + c0 + k) * NHEAD + o4);
            }
        }
        const float* fb = d_feats + (u + dy) * (FEAT * CB);
        #pragma unroll
        for (int j = 0; j < 5; j++) {
            int idx = tid + 256 * j;
            if (idx < 1040) {
                int m = idx >> 2, q4 = (idx & 3) << 2;
                int col = m; if (col > 255) col = 255;
                uint32_t d = (uint32_t)__cvta_generic_to_shared(&Bsb[buf][m * BSTR + q4]);
                cp16(d, fb + col * CB + c0 + q4);
            }
        }
        asm volatile("cp.async.commit_group;" ::: "memory");
    };

    float acc[3][4][4];
    #pragma unroll
    for (int mt = 0; mt < 3; mt++)
        #pragma unroll
        for (int nt = 0; nt < 4; nt++)
            #pragma unroll
            for (int i = 0; i < 4; i++) acc[mt][nt][i] = 0.0f;

    issue_fill(0, 0);

    for (int p = 0; p < 24; p++) {
        int cur = p & 1;
        asm volatile("cp.async.wait_group 0;" ::: "memory");   // fill(p) complete
        __syncthreads();                                       // visible + prev reads done
        if (p < 23) issue_fill(p + 1, cur ^ 1);                // overlaps compute(p)

        const float* As = Asb[cur];
        const float* Bs = Bsb[cur];
        #pragma unroll
        for (int ks = 0; ks < 2; ks++) {
            #pragma unroll
            for (int dx = 0; dx < 3; dx++) {
                uint32_t bf[4][2];
                #pragma unroll
                for (int nt = 0; nt < 4; nt++) {
                    int m = warp * 32 + nt * 8 + g + dx;
                    bf[nt][0] = __float_as_uint(Bs[m * BSTR + ks * 8 + q]);
                    bf[nt][1] = __float_as_uint(Bs[m * BSTR + ks * 8 + q + 4]);
                }
                const float* Ax = As + dx * AS_TAP;
                #pragma unroll
                for (int mt = 0; mt < 3; mt++) {
                    int ro = mt * 16;
                    uint32_t a0 = __float_as_uint(Ax[(ks * 8 + q    ) * AKS + ro + g    ]);
                    uint32_t a1 = __float_as_uint(Ax[(ks * 8 + q    ) * AKS + ro + g + 8]);
                    uint32_t a2 = __float_as_uint(Ax[(ks * 8 + q + 4) * AKS + ro + g    ]);
                    uint32_t a3 = __float_as_uint(Ax[(ks * 8 + q + 4) * AKS + ro + g + 8]);
                    #pragma unroll
                    for (int nt = 0; nt < 4; nt++)
                        mma_tf32(acc[mt][nt], a0, a1, a2, a3, bf[nt][0], bf[nt][1]);
                }
            }
        }
    }

    // ---- stage outputs (+bias) to smem: [pos][out], stride OSTR ----
    __syncthreads();                      // all MMA smem reads done; hsm reusable
    float* stage = hsm;                   // 256*49 floats = 50,176 B
    #pragma unroll
    for (int mt = 0; mt < 3; mt++) {
        float b0 = d_bfold[mt * 16 + g];
        float b1 = d_bfold[mt * 16 + g + 8];
        #pragma unroll
        for (int nt = 0; nt < 4; nt++) {
            #pragma unroll
            for (int c = 0; c < 2; c++) {
                int v = warp * 32 + nt * 8 + 2 * q + c;
                stage[v * OSTR + mt * 16 + g    ] = acc[mt][nt][0 + c] + b0;
                stage[v * OSTR + mt * 16 + g + 8] = acc[mt][nt][2 + c] + b1;
            }
        }
    }
    __syncthreads();                      // staging + skeyh init complete

    // ---- reduce pass1 parts (written by mega_prep fold blocks) ----
    for (int i = tid; i < NB_FOLD * K_GT; i += 256) {
        unsigned int k = d_gtpart[i];
        atomicMax(&skeyh[i & (K_GT - 1)], k);
    }
    __syncthreads();
    if (tid < K_GT) sgm[tid] = fdecode(skeyh[tid]);
    __syncthreads();

    float ming = sgm[0];
    #pragma unroll
    for (int g2 = 1; g2 < K_GT; g2++) ming = fminf(ming, sgm[g2]);

    // ---- fused loss over this row's 254x9 anchors ----
    float myc = 0.0f, mysel = 0.0f, mybox = 0.0f, mypos = 0.0f;
    for (int idx = tid; idx < FM * 9; idx += 256) {
        int v = idx / 9, a = idx - v * 9;
        float x1, y1, x2, y2; bool inside;
        anchor_box(u, v, a, x1, y1, x2, y2, inside);
        if (inside) {
            mysel += 1.0f;
            float mi = d_maxiou[(u * FM + v) * 9 + a];
            bool pos;
            if (mi >= 0.5f) {
                pos = true;
            } else if (mi >= ming) {
                bool best = false;
                #pragma unroll
                for (int g2 = 0; g2 < K_GT; g2++) {
                    float io = iou_exact(x1, y1, x2, y2,
                                         sgt[g2 * 4 + 0], sgt[g2 * 4 + 1],
                                         sgt[g2 * 4 + 2], sgt[g2 * 4 + 3]);
                    if (io == sgm[g2]) best = true;
                }
                pos = best;
            } else {
                pos = false;
            }
            float cls_v = stage[v * OSTR + a];
            myc += pos ? softplus_f(-cls_v) : softplus_f(cls_v);
            if (pos) {
                mypos += 1.0f;
                #pragma unroll
                for (int d = 0; d < 4; d++) {
                    float ab = fabsf(stage[v * OSTR + 9 + a * 4 + d]);
                    mybox += (ab < 1.0f) ? (0.5f * ab * ab) : (ab - 0.5f);
                }
            }
        }
    }

    #pragma unroll
    for (int off = 16; off > 0; off >>= 1) {
        myc   += __shfl_xor_sync(0xffffffffu, myc,   off);
        mysel += __shfl_xor_sync(0xffffffffu, mysel, off);
        mybox += __shfl_xor_sync(0xffffffffu, mybox, off);
        mypos += __shfl_xor_sync(0xffffffffu, mypos, off);
    }
    if (lane == 0) {
        atomicAdd(&sacc[0], (double)myc);
        atomicAdd(&sacc[1], (double)mysel);
        atomicAdd(&sacc[2], (double)mybox);
        atomicAdd(&sacc[3], (double)mypos);
    }
    __syncthreads();
    if (tid < 4) atomicAdd(&d_acc[tid], sacc[tid]);

    // ---- last-block finalize + self-reset (restores launch invariant) ----
    __syncthreads();
    if (tid == 0) {
        __threadfence();
        unsigned int v = atomicAdd(&d_cnt, 1u);
        slast = (v == gridDim.x - 1);
    }
    __syncthreads();
    if (slast && tid == 0) {
        double cls = d_acc[0] / d_acc[1];
        double box = d_acc[2] / d_acc[3];
        out[0] = (float)(cls + box);
        d_acc[0] = 0.0; d_acc[1] = 0.0; d_acc[2] = 0.0; d_acc[3] = 0.0;
        __threadfence();
        d_cnt = 0u;
    }
}

// ---------------- launch ----------------
extern "C" void kernel_launch(void* const* d_in, const int* in_sizes, int n_in,
                              void* d_out, int out_size) {
    const float* image = (const float*)d_in[0];
    const float* gt    = (const float*)d_in[1];
    const float* Wb    = (const float*)d_in[2];
    const float* bb    = (const float*)d_in[3];
    const float* Wi    = (const float*)d_in[4];
    const float* bi    = (const float*)d_in[5];
    const float* Wc    = (const float*)d_in[6];
    const float* bc    = (const float*)d_in[7];
    const float* Wr    = (const float*)d_in[8];
    const float* br    = (const float*)d_in[9];

    const int bsm = (2 * CB * BKS + CB) * sizeof(float);   // 53,760 B
    cudaFuncSetAttribute(mega_prep_kernel,
                         cudaFuncAttributeMaxDynamicSharedMemorySize, bsm);
    cudaFuncSetAttribute(head_mma_kernel,
                         cudaFuncAttributeMaxDynamicSharedMemorySize, HDSMEM);

    mega_prep_kernel<<<NB_PREP, 256, bsm>>>(image, Wb, bb, Wi, bi, Wc, bc, Wr, br, gt);
    head_mma_kernel<<<FM, 256, HDSMEM>>>(gt, (float*)d_out);
}

// round 17
// speedup vs baseline: 1.6967x; 1.6967x over previous
#include <cuda_runtime.h>
#include <math.h>
#include <stdint.h>

// ---------------- problem constants ----------------
#define IMG      1024
#define FEAT     256          // backbone output spatial
#define CB       128          // backbone channels
#define FM       254          // head conv output spatial
#define NHEAD    48           // 45 head outputs (9 cls + 36 reg), padded to 48
#define NPOS     (FM*FM)      // 64516 positions
#define N_ANCH   (NPOS*9)     // 580644 anchors
#define K_GT     16
#define NB_FOLD  288

// head kernel smem geometry (dy-outer: 24 phases, 3 dx taps per phase)
#define BSTR 20               // Bs row stride (words)
#define AKS  56               // As k-row stride (words)
#define AS_TAP   (16*AKS)     // 896 words per dx tap
#define AS_WORDS (3*AS_TAP)   // 2688 per buffer (3 dx taps)
#define BS_WORDS (260*BSTR)   // 5200 per buffer
#define HDSMEM  ((2*AS_WORDS + 2*BS_WORDS) * 4)   // 63104 B
#define OSTR 49               // output staging stride (conflict-free)

// ---------------- scratch (static device memory; no allocation) ----------------
// d_gtkey / d_acc / d_cnt are zero on first launch (static init) and reset by the
// last head block each launch -> the launch invariant holds across graph replays.
__device__ float d_feats[FEAT*FEAT*CB];        // 32 MB (tf32-rounded values)
__device__ float d_wf   [9*CB*NHEAD];          // folded head weights (tf32)
__device__ float d_bfold[NHEAD];
__device__ float d_maxiou[N_ANCH];             // per-anchor max IoU (pass1)
__device__ unsigned int d_gtkey[K_GT];
__device__ double d_acc[4];                    // cls_sum, sel_cnt, box_sum, pos_cnt
__device__ unsigned int d_cnt;

// ---------------- helpers ----------------
__device__ __forceinline__ unsigned int fkey(float f) {
    unsigned int u = __float_as_uint(f);
    return (u & 0x80000000u) ? ~u : (u | 0x80000000u);
}
__device__ __forceinline__ float fdecode(unsigned int k) {
    return (k & 0x80000000u) ? __uint_as_float(k & 0x7fffffffu) : __uint_as_float(~k);
}
__device__ __forceinline__ float to_tf32(float x) {
    uint32_t r;
    asm("cvt.rna.tf32.f32 %0, %1;" : "=r"(r) : "f"(x));
    return __uint_as_float(r);
}
__device__ __forceinline__ void cp16(uint32_t dst_s, const void* src) {
    asm volatile("cp.async.ca.shared.global [%0], [%1], 16;" :: "r"(dst_s), "l"(src));
}

// IoU with exact, non-contracted fp32 op order (matches the reference formula).
__device__ __forceinline__ float iou_exact(float ax1, float ay1, float ax2, float ay2,
                                           float gx1, float gy1, float gx2, float gy2) {
    const float g = 1.0f / 1024.0f;   // exact in fp32
    float s1 = __fmul_rn(__fadd_rn(__fadd_rn(ax2, -ax1), g),
                         __fadd_rn(__fadd_rn(ay2, -ay1), g));
    float s2 = __fmul_rn(__fadd_rn(__fadd_rn(gx2, -gx1), g),
                         __fadd_rn(__fadd_rn(gy2, -gy1), g));
    float xa = fmaxf(ax1, gx1), ya = fmaxf(ay1, gy1);
    float xb = fminf(ax2, gx2), yb = fminf(ay2, gy2);
    float iw = fmaxf(__fadd_rn(__fadd_rn(xb, -xa), g), 0.0f);
    float ih = fmaxf(__fadd_rn(__fadd_rn(yb, -ya), g), 0.0f);
    float inter = __fmul_rn(iw, ih);
    return __fdiv_rn(inter, __fadd_rn(__fadd_rn(s1, s2), -inter));
}

// anchor box (u -> x grid, v -> y grid, a -> ratio/scale)
__device__ __forceinline__ void anchor_box(int u, int v, int a,
                                           float& x1, float& y1, float& x2, float& y2,
                                           bool& inside) {
    const double STEP = 1.0 / 254.0;
    float cx = (float)((double)u * STEP);
    float cy = (float)((double)v * STEP);
    const float RAT[3] = {0.5f, 1.0f, 2.0f};
    const float SCL[3] = {0.2f, 0.4f, 0.7f};
    int ri = a / 3;
    int si = a - ri * 3;
    float r = sqrtf(RAT[ri]);
    float s = SCL[si];
    float w = __fmul_rn(s, r);
    float h = __fdiv_rn(s, r);
    float hwp = __fmul_rn(w, 0.5f);
    float hhp = __fmul_rn(h, 0.5f);
    float hwn = __fmul_rn(hwp, -1.0f);
    float hhn = __fmul_rn(hhp, -1.0f);
    x1 = __fadd_rn(cx, hwn);
    y1 = __fadd_rn(cy, hhn);
    x2 = __fadd_rn(cx, hwp);
    y2 = __fadd_rn(cy, hhp);
    inside = (x1 >= 0.0f) && (y1 >= 0.0f) && (x2 < 1.0f) && (y2 < 1.0f);
}

__device__ __forceinline__ float softplus_f(float x) {
    return fmaxf(x, 0.0f) + log1pf(expf(-fabsf(x)));
}

__device__ __forceinline__ void mma_tf32(float* acc,
                                         uint32_t a0, uint32_t a1, uint32_t a2, uint32_t a3,
                                         uint32_t b0, uint32_t b1) {
    asm volatile("mma.sync.aligned.m16n8k8.row.col.f32.tf32.tf32.f32 "
                 "{%0,%1,%2,%3}, {%4,%5,%6,%7}, {%8,%9}, {%0,%1,%2,%3};"
                 : "+f"(acc[0]), "+f"(acc[1]), "+f"(acc[2]), "+f"(acc[3])
                 : "r"(a0), "r"(a1), "r"(a2), "r"(a3), "r"(b0), "r"(b1));
}

// ---------------- kernel 1: fold head weights + pass1; block 288 = fold_b ----------------
__global__ void fold_w_kernel(const float* __restrict__ Wi,
                              const float* __restrict__ Wc,
                              const float* __restrict__ Wr,
                              const float* __restrict__ gt,
                              const float* __restrict__ bi,
                              const float* __restrict__ bc,
                              const float* __restrict__ br) {
    int tid = threadIdx.x;

    if (blockIdx.x == NB_FOLD) {
        // ---------- fold_b (8 warps, split-K) ----------
        int w = tid >> 5, lane = tid & 31;
        #pragma unroll
        for (int r = 0; r < 6; r++) {
            int o = w + 8 * r;            // 0..47
            float part = 0.0f;
            if (o < 45) {
                #pragma unroll
                for (int i = 0; i < 8; i++) {
                    int m = lane + 32 * i;
                    float bim = bi[m];
                    part += (o < 9) ? bim * Wc[m * 9 + o] : bim * Wr[m * 36 + (o - 9)];
                }
            }
            #pragma unroll
            for (int off = 16; off > 0; off >>= 1)
                part += __shfl_xor_sync(0xffffffffu, part, off);
            if (lane == 0) {
                float bias = (o < 9) ? bc[o] : (o < 45 ? br[o - 9] : 0.0f);
                d_bfold[o] = (o < 45) ? part + bias : 0.0f;
            }
        }
        return;
    }

    __shared__ float wrow[4][256];
    __shared__ float sgt[K_GT * 4];
    __shared__ unsigned int skey[K_GT];
    if (tid < K_GT * 4) sgt[tid] = gt[tid];
    if (tid < K_GT)     skey[tid] = 0u;

    int sb4 = tid >> 6;               // sub-block 0..3
    int t2  = tid & 63;
    int r   = blockIdx.x * 4 + sb4;   // 1152 rows total
    #pragma unroll
    for (int i = 0; i < 4; i++)
        wrow[sb4][t2 + 64 * i] = Wi[r * 256 + t2 + 64 * i];
    __syncthreads();
    if (t2 < NHEAD) {
        const float* w = wrow[sb4];
        float acc = 0.0f;
        if (t2 < 45) {
            float p0 = 0.f, p1 = 0.f, p2 = 0.f, p3 = 0.f;
            if (t2 < 9) {
                #pragma unroll 4
                for (int m = 0; m < 256; m += 4) {
                    p0 += w[m + 0] * Wc[(m + 0) * 9 + t2];
                    p1 += w[m + 1] * Wc[(m + 1) * 9 + t2];
                    p2 += w[m + 2] * Wc[(m + 2) * 9 + t2];
                    p3 += w[m + 3] * Wc[(m + 3) * 9 + t2];
                }
            } else {
                int o = t2 - 9;
                #pragma unroll 4
                for (int m = 0; m < 256; m += 4) {
                    p0 += w[m + 0] * Wr[(m + 0) * 36 + o];
                    p1 += w[m + 1] * Wr[(m + 1) * 36 + o];
                    p2 += w[m + 2] * Wr[(m + 2) * 36 + o];
                    p3 += w[m + 3] * Wr[(m + 3) * 36 + o];
                }
            }
            acc = (p0 + p1) + (p2 + p3);
        }
        d_wf[r * NHEAD + t2] = to_tf32(acc);
    }

    // ---- pass1 slice: per-gt max IoU + per-anchor maxiou store ----
    float mg[K_GT];
    #pragma unroll
    for (int g2 = 0; g2 < K_GT; g2++) mg[g2] = -1.0f;
    for (int n = blockIdx.x * 256 + tid; n < N_ANCH; n += NB_FOLD * 256) {
        int u = n / (FM * 9);
        int rem = n - u * (FM * 9);
        int v = rem / 9;
        int a = rem - v * 9;
        float x1, y1, x2, y2; bool inside;
        anchor_box(u, v, a, x1, y1, x2, y2, inside);
        float mi = -1.0f;
        if (inside) {
            #pragma unroll
            for (int g2 = 0; g2 < K_GT; g2++) {
                float io = iou_exact(x1, y1, x2, y2,
                                     sgt[g2 * 4 + 0], sgt[g2 * 4 + 1],
                                     sgt[g2 * 4 + 2], sgt[g2 * 4 + 3]);
                mi = fmaxf(mi, io);
                mg[g2] = fmaxf(mg[g2], io);
            }
        }
        d_maxiou[n] = mi;
    }
    int lane = tid & 31;
    #pragma unroll
    for (int g2 = 0; g2 < K_GT; g2++) {
        float m = mg[g2];
        #pragma unroll
        for (int off = 16; off > 0; off >>= 1)
            m = fmaxf(m, __shfl_xor_sync(0xffffffffu, m, off));
        if (lane == 0 && m > -1.0f) atomicMax(&skey[g2], fkey(m));
    }
    __syncthreads();
    if (tid < K_GT) atomicMax(&d_gtkey[tid], skey[tid]);
}

// ---------------- kernel 2: backbone conv as tf32 MMA GEMM ----------------
#define BKS 52
extern __shared__ float bsmem[];
__global__ __launch_bounds__(256) void backbone_mma_kernel(const float* __restrict__ img,
                                                           const float* __restrict__ Wb,
                                                           const float* __restrict__ bbias) {
    float* Wh = bsmem;                   // [128][BKS]
    float* Bs = bsmem + CB * BKS;        // [128][BKS]
    float* sb = bsmem + 2 * CB * BKS;    // [128]
    int tid = threadIdx.x;
    int b   = blockIdx.x;
    int oy  = b >> 1;
    int ox0 = (b & 1) * 128;

    #pragma unroll
    for (int i = tid; i < 6144; i += 256) {
        int o = i / 48, k = i - (i / 48) * 48;
        Wh[o * BKS + k] = to_tf32(Wb[k * CB + o]);
    }
    if (tid < 128) sb[tid] = bbias[tid];

    int oy4 = oy * 4;
    #pragma unroll
    for (int i = tid; i < 1536; i += 256) {
        int p = i / 12, j = i - (i / 12) * 12;
        const float* src = img + (oy4 + j / 3) * 3072 + (ox0 + p) * 12 + (j % 3) * 4;
        float4 v = *(const float4*)src;
        float* dst = &Bs[p * BKS + j * 4];
        dst[0] = to_tf32(v.x); dst[1] = to_tf32(v.y);
        dst[2] = to_tf32(v.z); dst[3] = to_tf32(v.w);
    }
    __syncthreads();

    int warp = tid >> 5, lane = tid & 31;
    int g = lane >> 2, q = lane & 3;

    float acc[8][2][4];
    #pragma unroll
    for (int mt = 0; mt < 8; mt++)
        #pragma unroll
        for (int nt = 0; nt < 2; nt++)
            #pragma unroll
            for (int i = 0; i < 4; i++) acc[mt][nt][i] = 0.0f;

    #pragma unroll
    for (int ks = 0; ks < 6; ks++) {
        uint32_t bf[2][2];
        #pragma unroll
        for (int nt = 0; nt < 2; nt++) {
            int m = warp * 16 + nt * 8 + g;
            bf[nt][0] = __float_as_uint(Bs[m * BKS + ks * 8 + q]);
            bf[nt][1] = __float_as_uint(Bs[m * BKS + ks * 8 + q + 4]);
        }
        #pragma unroll
        for (int mt = 0; mt < 8; mt++) {
            uint32_t a0 = __float_as_uint(Wh[(mt * 16 + g    ) * BKS + ks * 8 + q    ]);
            uint32_t a1 = __float_as_uint(Wh[(mt * 16 + g + 8) * BKS + ks * 8 + q    ]);
            uint32_t a2 = __float_as_uint(Wh[(mt * 16 + g    ) * BKS + ks * 8 + q + 4]);
            uint32_t a3 = __float_as_uint(Wh[(mt * 16 + g + 8) * BKS + ks * 8 + q + 4]);
            #pragma unroll
            for (int nt = 0; nt < 2; nt++)
                mma_tf32(acc[mt][nt], a0, a1, a2, a3, bf[nt][0], bf[nt][1]);
        }
    }

    #pragma unroll
    for (int mt = 0; mt < 8; mt++) {
        float b0 = sb[mt * 16 + g];
        float b1 = sb[mt * 16 + g + 8];
        #pragma unroll
        for (int nt = 0; nt < 2; nt++) {
            int p0 = warp * 16 + nt * 8 + 2 * q;
            #pragma unroll
            for (int c = 0; c < 2; c++) {
                int p = p0 + c;
                float* o = &d_feats[(oy * FEAT + ox0 + p) * CB + mt * 16 + g];
                o[0] = to_tf32(acc[mt][nt][0 + c] + b0);
                o[8] = to_tf32(acc[mt][nt][2 + c] + b1);
            }
        }
    }
}

// ---------------- kernel 3: head conv (1-sync pipeline) + pruned fused loss ----------------
extern __shared__ float hsm[];
__global__ __launch_bounds__(256, 2) void head_mma_kernel(const float* __restrict__ gt,
                                                          float* __restrict__ out) {
    float* Asb[2] = { hsm,              hsm + AS_WORDS };
    float* Bsb[2] = { hsm + 2*AS_WORDS, hsm + 2*AS_WORDS + BS_WORDS };
    __shared__ float sgt[K_GT * 4];
    __shared__ float sgm[K_GT];
    __shared__ double sacc[4];
    __shared__ bool slast;
    int tid  = threadIdx.x;
    int u    = blockIdx.x;
    int warp = tid >> 5, lane = tid & 31;
    int g = lane >> 2, q = lane & 3;

    if (tid < K_GT * 4) sgt[tid] = gt[tid];
    if (tid < 4)        sacc[tid] = 0.0;

    auto issue_fill = [&](int p, int buf) {
        int dy = p >> 3;
        int c0 = (p & 7) << 4;
        #pragma unroll
        for (int j = 0; j < 3; j++) {
            int idx = tid + 256 * j;
            if (idx < 576) {
                int dx = idx / 192, rem = idx - dx * 192;
                int k = rem / 12, o4 = (rem - (rem / 12) * 12) * 4;
                uint32_t d = (uint32_t)__cvta_generic_to_shared(
                    &Asb[buf][dx * AS_TAP + k * AKS + o4]);
                cp16(d, d_wf + ((dy * 3 + dx) * CB + c0 + k) * NHEAD + o4);
            }
        }
        const float* fb = d_feats + (u + dy) * (FEAT * CB);
        #pragma unroll
        for (int j = 0; j < 5; j++) {
            int idx = tid + 256 * j;
            if (idx < 1040) {
                int m = idx >> 2, q4 = (idx & 3) << 2;
                int col = m; if (col > 255) col = 255;
                uint32_t d = (uint32_t)__cvta_generic_to_shared(&Bsb[buf][m * BSTR + q4]);
                cp16(d, fb + col * CB + c0 + q4);
            }
        }
        asm volatile("cp.async.commit_group;" ::: "memory");
    };

    float acc[3][4][4];
    #pragma unroll
    for (int mt = 0; mt < 3; mt++)
        #pragma unroll
        for (int nt = 0; nt < 4; nt++)
            #pragma unroll
            for (int i = 0; i < 4; i++) acc[mt][nt][i] = 0.0f;

    issue_fill(0, 0);

    for (int p = 0; p < 24; p++) {
        int cur = p & 1;
        asm volatile("cp.async.wait_group 0;" ::: "memory");   // fill(p) complete
        __syncthreads();                                       // visible + prev reads done
        if (p < 23) issue_fill(p + 1, cur ^ 1);                // overlaps compute(p)

        const float* As = Asb[cur];
        const float* Bs = Bsb[cur];
        #pragma unroll
        for (int ks = 0; ks < 2; ks++) {
            #pragma unroll
            for (int dx = 0; dx < 3; dx++) {
                uint32_t bf[4][2];
                #pragma unroll
                for (int nt = 0; nt < 4; nt++) {
                    int m = warp * 32 + nt * 8 + g + dx;
                    bf[nt][0] = __float_as_uint(Bs[m * BSTR + ks * 8 + q]);
                    bf[nt][1] = __float_as_uint(Bs[m * BSTR + ks * 8 + q + 4]);
                }
                const float* Ax = As + dx * AS_TAP;
                #pragma unroll
                for (int mt = 0; mt < 3; mt++) {
                    int ro = mt * 16;
                    uint32_t a0 = __float_as_uint(Ax[(ks * 8 + q    ) * AKS + ro + g    ]);
                    uint32_t a1 = __float_as_uint(Ax[(ks * 8 + q    ) * AKS + ro + g + 8]);
                    uint32_t a2 = __float_as_uint(Ax[(ks * 8 + q + 4) * AKS + ro + g    ]);
                    uint32_t a3 = __float_as_uint(Ax[(ks * 8 + q + 4) * AKS + ro + g + 8]);
                    #pragma unroll
                    for (int nt = 0; nt < 4; nt++)
                        mma_tf32(acc[mt][nt], a0, a1, a2, a3, bf[nt][0], bf[nt][1]);
                }
            }
        }
    }

    // ---- stage outputs (+bias) to smem: [pos][out], stride OSTR ----
    __syncthreads();                      // all MMA smem reads done; hsm reusable
    float* stage = hsm;                   // 256*49 floats = 50,176 B
    #pragma unroll
    for (int mt = 0; mt < 3; mt++) {
        float b0 = d_bfold[mt * 16 + g];
        float b1 = d_bfold[mt * 16 + g + 8];
        #pragma unroll
        for (int nt = 0; nt < 4; nt++) {
            #pragma unroll
            for (int c = 0; c < 2; c++) {
                int v = warp * 32 + nt * 8 + 2 * q + c;
                stage[v * OSTR + mt * 16 + g    ] = acc[mt][nt][0 + c] + b0;
                stage[v * OSTR + mt * 16 + g + 8] = acc[mt][nt][2 + c] + b1;
            }
        }
    }
    if (tid < K_GT) sgm[tid] = fdecode(d_gtkey[tid]);   // pass1 finalized in fold kernel
    __syncthreads();

    float ming = sgm[0];
    #pragma unroll
    for (int g2 = 1; g2 < K_GT; g2++) ming = fminf(ming, sgm[g2]);

    // ---- fused loss over this row's 254x9 anchors ----
    float myc = 0.0f, mysel = 0.0f, mybox = 0.0f, mypos = 0.0f;
    for (int idx = tid; idx < FM * 9; idx += 256) {
        int v = idx / 9, a = idx - v * 9;
        float x1, y1, x2, y2; bool inside;
        anchor_box(u, v, a, x1, y1, x2, y2, inside);
        if (inside) {
            mysel += 1.0f;
            float mi = d_maxiou[(u * FM + v) * 9 + a];
            bool pos;
            if (mi >= 0.5f) {
                pos = true;
            } else if (mi >= ming) {
                bool best = false;
                #pragma unroll
                for (int g2 = 0; g2 < K_GT; g2++) {
                    float io = iou_exact(x1, y1, x2, y2,
                                         sgt[g2 * 4 + 0], sgt[g2 * 4 + 1],
                                         sgt[g2 * 4 + 2], sgt[g2 * 4 + 3]);
                    if (io == sgm[g2]) best = true;
                }
                pos = best;
            } else {
                pos = false;
            }
            float cls_v = stage[v * OSTR + a];
            myc += pos ? softplus_f(-cls_v) : softplus_f(cls_v);
            if (pos) {
                mypos += 1.0f;
                #pragma unroll
                for (int d = 0; d < 4; d++) {
                    float ab = fabsf(stage[v * OSTR + 9 + a * 4 + d]);
                    mybox += (ab < 1.0f) ? (0.5f * ab * ab) : (ab - 0.5f);
                }
            }
        }
    }

    #pragma unroll
    for (int off = 16; off > 0; off >>= 1) {
        myc   += __shfl_xor_sync(0xffffffffu, myc,   off);
        mysel += __shfl_xor_sync(0xffffffffu, mysel, off);
        mybox += __shfl_xor_sync(0xffffffffu, mybox, off);
        mypos += __shfl_xor_sync(0xffffffffu, mypos, off);
    }
    if (lane == 0) {
        atomicAdd(&sacc[0], (double)myc);
        atomicAdd(&sacc[1], (double)mysel);
        atomicAdd(&sacc[2], (double)mybox);
        atomicAdd(&sacc[3], (double)mypos);
    }
    __syncthreads();
    if (tid < 4) atomicAdd(&d_acc[tid], sacc[tid]);

    // ---- last-block finalize + self-reset (restores launch invariant) ----
    __syncthreads();
    if (tid == 0) {
        __threadfence();
        unsigned int v = atomicAdd(&d_cnt, 1u);
        slast = (v == gridDim.x - 1);
    }
    __syncthreads();
    if (slast && tid == 0) {
        double cls = d_acc[0] / d_acc[1];
        double box = d_acc[2] / d_acc[3];
        out[0] = (float)(cls + box);
        d_acc[0] = 0.0; d_acc[1] = 0.0; d_acc[2] = 0.0; d_acc[3] = 0.0;
        #pragma unroll
        for (int g2 = 0; g2 < K_GT; g2++) d_gtkey[g2] = 0u;   // all blocks read sgm before ticketing
        __threadfence();
        d_cnt = 0u;
    }
}

// ---------------- launch ----------------
extern "C" void kernel_launch(void* const* d_in, const int* in_sizes, int n_in,
                              void* d_out, int out_size) {
    const float* image = (const float*)d_in[0];
    const float* gt    = (const float*)d_in[1];
    const float* Wb    = (const float*)d_in[2];
    const float* bb    = (const float*)d_in[3];
    const float* Wi    = (const float*)d_in[4];
    const float* bi    = (const float*)d_in[5];
    const float* Wc    = (const float*)d_in[6];
    const float* bc    = (const float*)d_in[7];
    const float* Wr    = (const float*)d_in[8];
    const float* br    = (const float*)d_in[9];

    const int bsm = (2 * CB * BKS + CB) * sizeof(float);   // 53,760 B
    cudaFuncSetAttribute(backbone_mma_kernel,
                         cudaFuncAttributeMaxDynamicSharedMemorySize, bsm);
    cudaFuncSetAttribute(head_mma_kernel,
                         cudaFuncAttributeMaxDynamicSharedMemorySize, HDSMEM);

    fold_w_kernel<<<NB_FOLD + 1, 256>>>(Wi, Wc, Wr, gt, bi, bc, br);
    backbone_mma_kernel<<<512, 256, bsm>>>(image, Wb, bb);
    head_mma_kernel<<<FM, 256, HDSMEM>>>(gt, (float*)d_out);
}